// round 11
// baseline (speedup 1.0000x reference)
#include <cuda_runtime.h>
#include <cuda_fp16.h>

#define HH 128
#define WW 128
#define BB 64
#define OO 32
#define NPIX (HH * WW)
#define NBUILD 512                   // first 512 linear bids are builders (all in wave 1)
#define NCTAS (HH * OO)
#define TPB 256

// 8 MB quad tap table: g_Q[pix][lane(b-pair)] = {Ia, Ic, Ib, Id} as 4x half2
__device__ uint4 g_Q[NPIX * 32];
__device__ float4 g_aff[OO];
__device__ float2 g_off[OO];
__device__ unsigned g_cnt[32];       // builder-done counters (spread over 32 addresses)
__device__ unsigned g_fin[32];       // CTA-finished counters (for replay-safe reset)

__global__ __launch_bounds__(TPB, 8) void fused_kernel(
    const float* __restrict__ X,
    const float* __restrict__ eps,
    const float* __restrict__ tmin,
    const float* __restrict__ tmax,
    float* __restrict__ out)
{
    __shared__ __half2 plane[WW][32];        // main: swizzled result plane (16 KB)
    __shared__ __half2 s2[2][33][33];        // build: staging tile (8.7 KB)
    __shared__ int s_go;

    const int tid  = threadIdx.x;
    const int lane = tid & 31;
    const int warp = tid >> 5;               // 0..7
    const int y = blockIdx.x;
    const int o = blockIdx.y;
    const unsigned bid = blockIdx.x + blockIdx.y * HH;   // linear, x-fastest

    // ================= build phase (first 512 bids, all resident in wave 1) ====
    if (bid < NBUILD) {
        if (bid == 0 && tid < OO) {          // affine setup rides on bid 0
            const int oo = tid;
            float th[7];
            #pragma unroll
            for (int i = 0; i < 7; i++) {
                const float mn = tmin[i];
                th[i] = fmaf(tmax[i] - mn, eps[oo * 7 + i], mn);
            }
            float s, c;
            sincosf(th[0], &s, &c);
            const float sx = th[1], sy = th[2], pX = th[3], pY = th[4], tx = th[5], ty = th[6];
            const float a00 = c * sx - s * pY;
            const float a01 = c * pX - s * sy;
            const float a10 = s * sx + c * pY;
            const float a11 = s * pX + c * sy;
            g_aff[oo] = make_float4(a00, a10, a01, a11);
            g_off[oo] = make_float2(63.5f * (tx + 1.0f - a00 - a01),
                                    63.5f * (ty + 1.0f - a10 - a11));
        }

        const int q  = o;                    // x-quadrant 0..3
        const int yn = min(y + 1, HH - 1);

        // stage rows (y, y+1), local cols [0,33), all 64 b; unrolled -> 16 LDGs in flight
        #pragma unroll
        for (int t = 0; t < 16; t++) {
            const int task = warp + t * 8;   // 0..127
            const int r = task >> 6;
            const int b = task & (BB - 1);
            const float* src = X + ((size_t)b * HH + (r ? yn : y)) * WW;
            __half* hp = reinterpret_cast<__half*>(&s2[r][0][b >> 1]) + (b & 1);
            const int gx = min(q * 32 + lane, WW - 1);
            hp[lane * 66] = __float2half(src[gx]);
            if (lane == 0) {
                const int gx2 = min(q * 32 + 32, WW - 1);
                hp[32 * 66] = __float2half(src[gx2]);
            }
        }
        __syncthreads();

        // emit quad records: warp handles xl = 4w..4w+3; lane = b-pair
        uint4* dst = g_Q + ((size_t)y * WW + q * 32) * 32;
        #pragma unroll
        for (int ii = 0; ii < 4; ii++) {
            const int xl = warp * 4 + ii;
            uint4 qq;
            qq.x = *reinterpret_cast<const unsigned*>(&s2[0][xl][lane]);
            qq.y = *reinterpret_cast<const unsigned*>(&s2[0][xl + 1][lane]);
            qq.z = *reinterpret_cast<const unsigned*>(&s2[1][xl][lane]);
            qq.w = *reinterpret_cast<const unsigned*>(&s2[1][xl + 1][lane]);
            dst[xl * 32 + lane] = qq;
        }
        __threadfence();                     // publish g_Q (+ g_aff) device-wide
        __syncthreads();
        if (tid == 0) atomicAdd(&g_cnt[bid & 31], 1u);   // 16 atomics per address total
    }

    // ================= barrier: plain-load polling, no atomic spin =============
    if (warp == 0) {
        volatile unsigned* vc = g_cnt;
        for (;;) {
            unsigned v = vc[lane];
            unsigned sum = __reduce_add_sync(0xffffffffu, v);
            if (sum >= NBUILD) break;
            __nanosleep(128);
        }
        __threadfence();                     // acquire builders' writes
        if (tid == 0) s_go = 1;
    }
    __syncthreads();
    (void)s_go;

    // ================= main phase (all 4096 CTAs) ==============================
    const float4 A  = g_aff[o];
    const float2 Of = g_off[o];
    const float a00 = A.x, a10 = A.y, a01 = A.z, a11 = A.w;

    const float rowx = fmaf(a01, (float)y, Of.x);
    const float rowy = fmaf(a11, (float)y, Of.y);

    #pragma unroll 8
    for (int i = 0; i < 16; i++) {
        const int x = warp * 16 + i;

        const float cx = fminf(fmaxf(fmaf(a00, (float)x, rowx), 0.0f), 126.99999f);
        const float cy = fminf(fmaxf(fmaf(a10, (float)x, rowy), 0.0f), 126.99999f);
        const int x0 = (int)cx;
        const int y0 = (int)cy;
        const __half2 wx2 = __float2half2_rn(cx - (float)x0);
        const __half2 wy2 = __float2half2_rn(cy - (float)y0);

        // ONE LDG.128 fetches all 4 taps for this lane's b-pair
        const uint4 qv = g_Q[(unsigned)((y0 * WW + x0) * 32 + lane)];
        const __half2 Ia = *reinterpret_cast<const __half2*>(&qv.x);
        const __half2 Ic = *reinterpret_cast<const __half2*>(&qv.y);
        const __half2 Ib = *reinterpret_cast<const __half2*>(&qv.z);
        const __half2 Id = *reinterpret_cast<const __half2*>(&qv.w);

        const __half2 t0 = __hfma2(wx2, __hsub2(Ic, Ia), Ia);
        const __half2 t1 = __hfma2(wx2, __hsub2(Id, Ib), Ib);
        const __half2 r  = __hfma2(wy2, __hsub2(t1, t0), t0);

        plane[x][lane ^ (x & 31)] = r;       // bank permutation: conflict-free
    }

    __syncthreads();

    // writeout: warp w handles b-pairs p = 4w..4w+3; lane owns x = 4*lane..4*lane+3
    #pragma unroll
    for (int pp = 0; pp < 4; pp++) {
        const int p = warp * 4 + pp;         // b = 2p, 2p+1
        float4 lo, hi;
        {
            const int xb = 4 * lane;
            const float2 v0 = __half22float2(plane[xb + 0][p ^ ((xb + 0) & 31)]);
            const float2 v1 = __half22float2(plane[xb + 1][p ^ ((xb + 1) & 31)]);
            const float2 v2 = __half22float2(plane[xb + 2][p ^ ((xb + 2) & 31)]);
            const float2 v3 = __half22float2(plane[xb + 3][p ^ ((xb + 3) & 31)]);
            lo = make_float4(v0.x, v1.x, v2.x, v3.x);
            hi = make_float4(v0.y, v1.y, v2.y, v3.y);
        }
        float* __restrict__ d0 = out + (size_t)(o * BB + 2 * p) * NPIX + y * WW;
        reinterpret_cast<float4*>(d0)[lane]         = lo;   // STG.128, coalesced
        reinterpret_cast<float4*>(d0 + NPIX)[lane]  = hi;
    }

    // ================= replay-safe reset (off critical path) ===================
    if (tid == 0) atomicAdd(&g_fin[bid & 31], 1u);
    if (bid == 0 && tid == 0) {
        volatile unsigned* vf = g_fin;
        for (;;) {
            unsigned sum = 0;
            #pragma unroll
            for (int i = 0; i < 32; i++) sum += vf[i];
            if (sum >= NCTAS) break;
            __nanosleep(256);
        }
        #pragma unroll
        for (int i = 0; i < 32; i++) { g_cnt[i] = 0u; g_fin[i] = 0u; }
        __threadfence();
    }
}

extern "C" void kernel_launch(void* const* d_in, const int* in_sizes, int n_in,
                              void* d_out, int out_size)
{
    const float* X    = (const float*)d_in[0];
    const float* eps  = (const float*)d_in[1];
    const float* tmin = (const float*)d_in[2];
    const float* tmax = (const float*)d_in[3];
    float* out = (float*)d_out;

    dim3 grid(HH, OO);                       // 4096 CTAs, builders = first 512 bids
    fused_kernel<<<grid, TPB>>>(X, eps, tmin, tmax, out);
}

// round 12
// speedup vs baseline: 1.1461x; 1.1461x over previous
#include <cuda_runtime.h>
#include <cuda_fp16.h>

#define HH 128
#define WW 128
#define BB 64
#define OO 32
#define NPIX (HH * WW)
#define TPB 256

// 8 MB quad tap table: g_Q[pix][lane(b-pair)] = {Ia, Ic, Ib, Id} as 4x half2
//   Ia=(x,y) Ic=(x+1,y) Ib=(x,y+1) Id=(x+1,y+1), neighbors clamped to edge
__device__ uint4 g_Q[NPIX * 32];
__device__ float4 g_aff[OO];
__device__ float2 g_off[OO];

// grid = HH*4 + 1 blocks of 256.  bid < HH*4: y = bid>>2, x-quadrant q = bid&3.
__global__ __launch_bounds__(256) void build_kernel(
    const float* __restrict__ X,
    const float* __restrict__ eps,
    const float* __restrict__ tmin,
    const float* __restrict__ tmax)
{
    const int bid = blockIdx.x;
    if (bid == HH * 4) {                    // affine setup block
        const int o = threadIdx.x;
        if (o < OO) {
            float th[7];
            #pragma unroll
            for (int i = 0; i < 7; i++) {
                const float mn = tmin[i];
                th[i] = fmaf(tmax[i] - mn, eps[o * 7 + i], mn);
            }
            float s, c;
            sincosf(th[0], &s, &c);
            const float sx = th[1], sy = th[2], pX = th[3], pY = th[4], tx = th[5], ty = th[6];
            const float a00 = c * sx - s * pY;
            const float a01 = c * pX - s * sy;
            const float a10 = s * sx + c * pY;
            const float a11 = s * pX + c * sy;
            // pixel coords: px = a00*x + a01*y + offx   [(2/127)*63.5 == 1 exactly]
            g_aff[o] = make_float4(a00, a10, a01, a11);
            g_off[o] = make_float2(63.5f * (tx + 1.0f - a00 - a01),
                                   63.5f * (ty + 1.0f - a10 - a11));
        }
        return;
    }

    // staging tile: rows (y, y+1) x local cols [0,33) x 64 b (as 32 b-pairs + pad)
    __shared__ __half2 s2[2][33][33];       // [r][xl][bpair], pad -> conflict-free
    const int y    = bid >> 2;
    const int q    = bid & 3;
    const int yn   = min(y + 1, HH - 1);
    const int lane = threadIdx.x & 31;
    const int warp = threadIdx.x >> 5;      // 0..7

    // stage: 128 (r,b) tasks over 8 warps; unrolled -> 16 LDGs in flight per warp
    #pragma unroll
    for (int t = 0; t < 16; t++) {
        const int task = warp + t * 8;      // 0..127
        const int r = task >> 6;
        const int b = task & (BB - 1);
        const float* src = X + ((size_t)b * HH + (r ? yn : y)) * WW;
        __half* hp = reinterpret_cast<__half*>(&s2[r][0][b >> 1]) + (b & 1);
        const int gx = min(q * 32 + lane, WW - 1);
        hp[lane * 66] = __float2half(src[gx]);
        if (lane == 0) {
            const int gx2 = min(q * 32 + 32, WW - 1);
            hp[32 * 66] = __float2half(src[gx2]);
        }
    }
    __syncthreads();

    // emit quad records: warp handles xl = 4w..4w+3; lane = b-pair
    uint4* dst = g_Q + ((size_t)y * WW + q * 32) * 32;
    #pragma unroll
    for (int ii = 0; ii < 4; ii++) {
        const int xl = warp * 4 + ii;
        uint4 qq;
        qq.x = *reinterpret_cast<const unsigned*>(&s2[0][xl][lane]);
        qq.y = *reinterpret_cast<const unsigned*>(&s2[0][xl + 1][lane]);
        qq.z = *reinterpret_cast<const unsigned*>(&s2[1][xl][lane]);
        qq.w = *reinterpret_cast<const unsigned*>(&s2[1][xl + 1][lane]);
        dst[xl * 32 + lane] = qq;           // 512B contiguous per warp
    }
}

__global__ __launch_bounds__(TPB, 8) void dalayer_kernel(float* __restrict__ out)
{
    // swizzled half2 plane: [x][col] holds b-pair (col ^ (x&31))
    __shared__ __half2 plane[WW][32];       // 16 KB

    const int tid  = threadIdx.x;
    const int lane = tid & 31;
    const int warp = tid >> 5;              // 0..7
    const int y = blockIdx.x;
    const int o = blockIdx.y;

    const float4 A  = g_aff[o];
    const float2 Of = g_off[o];
    const float a00 = A.x, a10 = A.y, a01 = A.z, a11 = A.w;

    const float rowx = fmaf(a01, (float)y, Of.x);
    const float rowy = fmaf(a11, (float)y, Of.y);

    // ---- compute: warp w handles x = 16w..16w+15; lane = b-pair ----
    #pragma unroll
    for (int i = 0; i < 16; i++) {
        const int x = warp * 16 + i;

        const float cx = fminf(fmaxf(fmaf(a00, (float)x, rowx), 0.0f), 126.99999f);
        const float cy = fminf(fmaxf(fmaf(a10, (float)x, rowy), 0.0f), 126.99999f);
        const int x0 = (int)cx;
        const int y0 = (int)cy;
        const __half2 wx2 = __float2half2_rn(cx - (float)x0);
        const __half2 wy2 = __float2half2_rn(cy - (float)y0);

        // ONE LDG.128 fetches all 4 taps for this lane's b-pair
        const uint4 qv = g_Q[(unsigned)((y0 * WW + x0) * 32 + lane)];
        const __half2 Ia = *reinterpret_cast<const __half2*>(&qv.x);
        const __half2 Ic = *reinterpret_cast<const __half2*>(&qv.y);
        const __half2 Ib = *reinterpret_cast<const __half2*>(&qv.z);
        const __half2 Id = *reinterpret_cast<const __half2*>(&qv.w);

        const __half2 t0 = __hfma2(wx2, __hsub2(Ic, Ia), Ia);
        const __half2 t1 = __hfma2(wx2, __hsub2(Id, Ib), Ib);
        const __half2 r  = __hfma2(wy2, __hsub2(t1, t0), t0);

        plane[x][lane ^ (x & 31)] = r;       // bank permutation: conflict-free
    }

    __syncthreads();

    // ---- writeout: warp w handles b-pairs p = 4w..4w+3; lane owns x = 4l..4l+3 ----
    #pragma unroll
    for (int pp = 0; pp < 4; pp++) {
        const int p = warp * 4 + pp;         // b = 2p, 2p+1
        float4 lo, hi;
        {
            const int xb = 4 * lane;
            const float2 v0 = __half22float2(plane[xb + 0][p ^ ((xb + 0) & 31)]);
            const float2 v1 = __half22float2(plane[xb + 1][p ^ ((xb + 1) & 31)]);
            const float2 v2 = __half22float2(plane[xb + 2][p ^ ((xb + 2) & 31)]);
            const float2 v3 = __half22float2(plane[xb + 3][p ^ ((xb + 3) & 31)]);
            lo = make_float4(v0.x, v1.x, v2.x, v3.x);
            hi = make_float4(v0.y, v1.y, v2.y, v3.y);
        }
        float* __restrict__ d0 = out + (size_t)(o * BB + 2 * p) * NPIX + y * WW;
        reinterpret_cast<float4*>(d0)[lane]        = lo;   // STG.128, coalesced
        reinterpret_cast<float4*>(d0 + NPIX)[lane] = hi;
    }
}

extern "C" void kernel_launch(void* const* d_in, const int* in_sizes, int n_in,
                              void* d_out, int out_size)
{
    const float* X    = (const float*)d_in[0];
    const float* eps  = (const float*)d_in[1];
    const float* tmin = (const float*)d_in[2];
    const float* tmax = (const float*)d_in[3];
    float* out = (float*)d_out;

    build_kernel<<<HH * 4 + 1, 256>>>(X, eps, tmin, tmax);

    dim3 grid(HH, OO);                       // 128 x 32 CTAs
    dalayer_kernel<<<grid, TPB>>>(out);
}

// round 13
// speedup vs baseline: 1.2665x; 1.1050x over previous
#include <cuda_runtime.h>
#include <cuda_fp16.h>

#define HH 128
#define WW 128
#define BB 64
#define OO 32
#define NPIX (HH * WW)
#define TPB 256

// 8 MB quad tap table: g_Q[pix][lane(b-pair)] = {Ia, Ic, Ib, Id} as 4x half2
//   Ia=(x,y) Ic=(x+1,y) Ib=(x,y+1) Id=(x+1,y+1), neighbors clamped to edge
__device__ uint4 g_Q[NPIX * 32];
__device__ float4 g_aff[OO];
__device__ float2 g_off[OO];

// grid = HH*4 + 1 blocks of 256.  bid < HH*4: y = bid>>2, x-quadrant q = bid&3.
__global__ __launch_bounds__(256) void build_kernel(
    const float* __restrict__ X,
    const float* __restrict__ eps,
    const float* __restrict__ tmin,
    const float* __restrict__ tmax)
{
    const int bid = blockIdx.x;
    if (bid == HH * 4) {                    // affine setup block
        const int o = threadIdx.x;
        if (o < OO) {
            float th[7];
            #pragma unroll
            for (int i = 0; i < 7; i++) {
                const float mn = tmin[i];
                th[i] = fmaf(tmax[i] - mn, eps[o * 7 + i], mn);
            }
            float s, c;
            sincosf(th[0], &s, &c);
            const float sx = th[1], sy = th[2], pX = th[3], pY = th[4], tx = th[5], ty = th[6];
            const float a00 = c * sx - s * pY;
            const float a01 = c * pX - s * sy;
            const float a10 = s * sx + c * pY;
            const float a11 = s * pX + c * sy;
            // pixel coords: px = a00*x + a01*y + offx   [(2/127)*63.5 == 1 exactly]
            g_aff[o] = make_float4(a00, a10, a01, a11);
            g_off[o] = make_float2(63.5f * (tx + 1.0f - a00 - a01),
                                   63.5f * (ty + 1.0f - a10 - a11));
        }
        cudaTriggerProgrammaticLaunchCompletion();
        return;
    }

    // staging tile: rows (y, y+1) x local cols [0,33) x 64 b (as 32 b-pairs + pad)
    __shared__ __half2 s2[2][33][33];       // [r][xl][bpair], pad -> conflict-free
    const int y    = bid >> 2;
    const int q    = bid & 3;
    const int yn   = min(y + 1, HH - 1);
    const int lane = threadIdx.x & 31;
    const int warp = threadIdx.x >> 5;      // 0..7

    // stage: 128 (r,b) tasks over 8 warps; unrolled -> 16 LDGs in flight per warp
    #pragma unroll
    for (int t = 0; t < 16; t++) {
        const int task = warp + t * 8;      // 0..127
        const int r = task >> 6;
        const int b = task & (BB - 1);
        const float* src = X + ((size_t)b * HH + (r ? yn : y)) * WW;
        __half* hp = reinterpret_cast<__half*>(&s2[r][0][b >> 1]) + (b & 1);
        const int gx = min(q * 32 + lane, WW - 1);
        hp[lane * 66] = __float2half(src[gx]);
        if (lane == 0) {
            const int gx2 = min(q * 32 + 32, WW - 1);
            hp[32 * 66] = __float2half(src[gx2]);
        }
    }
    __syncthreads();

    // emit quad records: warp handles xl = 4w..4w+3; lane = b-pair
    uint4* dst = g_Q + ((size_t)y * WW + q * 32) * 32;
    #pragma unroll
    for (int ii = 0; ii < 4; ii++) {
        const int xl = warp * 4 + ii;
        uint4 qq;
        qq.x = *reinterpret_cast<const unsigned*>(&s2[0][xl][lane]);
        qq.y = *reinterpret_cast<const unsigned*>(&s2[0][xl + 1][lane]);
        qq.z = *reinterpret_cast<const unsigned*>(&s2[1][xl][lane]);
        qq.w = *reinterpret_cast<const unsigned*>(&s2[1][xl + 1][lane]);
        dst[xl * 32 + lane] = qq;           // 512B contiguous per warp
    }
    cudaTriggerProgrammaticLaunchCompletion();
}

__global__ __launch_bounds__(TPB, 8) void dalayer_kernel(float* __restrict__ out)
{
    // swizzled half2 plane: [x][col] holds b-pair (col ^ (x&31))
    __shared__ __half2 plane[WW][32];       // 16 KB

    const int tid  = threadIdx.x;
    const int lane = tid & 31;
    const int warp = tid >> 5;              // 0..7
    const int y = blockIdx.x;
    const int o = blockIdx.y;

    // wait for build_kernel's g_aff/g_off/g_Q to be visible (PDL dependency)
    cudaGridDependencySynchronize();

    const float4 A  = g_aff[o];
    const float2 Of = g_off[o];
    const float a00 = A.x, a10 = A.y, a01 = A.z, a11 = A.w;

    const float rowx = fmaf(a01, (float)y, Of.x);
    const float rowy = fmaf(a11, (float)y, Of.y);

    // ---- compute: warp w handles x = 16w..16w+15; lane = b-pair ----
    #pragma unroll 8
    for (int i = 0; i < 16; i++) {
        const int x = warp * 16 + i;

        const float cx = fminf(fmaxf(fmaf(a00, (float)x, rowx), 0.0f), 126.99999f);
        const float cy = fminf(fmaxf(fmaf(a10, (float)x, rowy), 0.0f), 126.99999f);
        const int x0 = (int)cx;
        const int y0 = (int)cy;
        const __half2 wx2 = __float2half2_rn(cx - (float)x0);
        const __half2 wy2 = __float2half2_rn(cy - (float)y0);

        // ONE LDG.128 fetches all 4 taps for this lane's b-pair
        const uint4 qv = g_Q[(unsigned)((y0 * WW + x0) * 32 + lane)];
        const __half2 Ia = *reinterpret_cast<const __half2*>(&qv.x);
        const __half2 Ic = *reinterpret_cast<const __half2*>(&qv.y);
        const __half2 Ib = *reinterpret_cast<const __half2*>(&qv.z);
        const __half2 Id = *reinterpret_cast<const __half2*>(&qv.w);

        const __half2 t0 = __hfma2(wx2, __hsub2(Ic, Ia), Ia);
        const __half2 t1 = __hfma2(wx2, __hsub2(Id, Ib), Ib);
        const __half2 r  = __hfma2(wy2, __hsub2(t1, t0), t0);

        plane[x][lane ^ (x & 31)] = r;       // bank permutation: conflict-free
    }

    __syncthreads();

    // ---- writeout: warp w handles b-pairs p = 4w..4w+3; lane = x mod 32 ----
    #pragma unroll
    for (int pp = 0; pp < 4; pp++) {
        const int p = warp * 4 + pp;         // b = 2p, 2p+1
        float* __restrict__ d0 = out + (size_t)(o * BB + 2 * p) * NPIX + y * WW;
        float* __restrict__ d1 = d0 + NPIX;
        #pragma unroll
        for (int j = 0; j < 4; j++) {
            const int x = j * 32 + lane;
            const float2 v = __half22float2(plane[x][p ^ lane]); // bank perm: conflict-free
            d0[x] = v.x;
            d1[x] = v.y;
        }
    }
}

extern "C" void kernel_launch(void* const* d_in, const int* in_sizes, int n_in,
                              void* d_out, int out_size)
{
    const float* X    = (const float*)d_in[0];
    const float* eps  = (const float*)d_in[1];
    const float* tmin = (const float*)d_in[2];
    const float* tmax = (const float*)d_in[3];
    float* out = (float*)d_out;

    build_kernel<<<HH * 4 + 1, 256>>>(X, eps, tmin, tmax);

    // main kernel with programmatic dependent launch: overlaps launch latency
    // with build's tail; cudaGridDependencySynchronize() gates data reads.
    cudaLaunchConfig_t cfg = {};
    cfg.gridDim  = dim3(HH, OO);
    cfg.blockDim = dim3(TPB);
    cudaLaunchAttribute attrs[1];
    attrs[0].id = cudaLaunchAttributeProgrammaticStreamSerialization;
    attrs[0].val.programmaticStreamSerializationAllowed = 1;
    cfg.attrs = attrs;
    cfg.numAttrs = 1;
    cudaLaunchKernelEx(&cfg, dalayer_kernel, out);
}